// round 14
// baseline (speedup 1.0000x reference)
#include <cuda_runtime.h>
#include <cuda_bf16.h>
#include <cuda_fp16.h>
#include <cstdint>

// Problem constants (fixed by the dataset)
#define NN     401408          // nodes
#define EE     3211264         // edges
#define CAP    40              // slots per node (indegree ~ Poisson(8))
#define OVF_CAP 65536
#define KTOT   50176           // 784*64
#define NGRAPH 512
#define SPLITS 37              // split-K partitions over 1568 K-chunks of 32

typedef unsigned long long u64;

// ---------------- device scratch (static, no allocations) ----------------
// g_cnt / g_ovf_n rely on CUDA zero-init for call 1; later kernels of each
// call re-zero them for the next call (k_l2f/k_l2 -> g_cnt, k_hgemm -> g_ovf_n).
__device__ int   g_cnt[NN];
__device__ float g_dinv[NN];
__device__ float g_xd[NN];                                     // x*dinv
__device__ int   g_slots[(size_t)CAP * NN];                    // slot-major
__device__ __align__(16) float g_h1[(size_t)NN * 32];          // fallback path only
__device__ __align__(8)  float2 g_ac[NN];                      // (relu(tt)*di, min(tt,0)*di)
__device__ __align__(8)  float2 g_s[NN];                       // (s1, s2) post-aggregation
__device__ float g_P[64], g_Q[64];
__device__ __align__(16) __half g_h2f[(size_t)NGRAPH * KTOT];  // fallback path only
__device__ __align__(16) __half g_fc1f[(size_t)128 * KTOT];    // B^T fp16 [n][k]
__device__ __align__(16) float g_part[(size_t)SPLITS * NGRAPH * 128];
__device__ int   g_ovf_n;
__device__ int   g_ovf_src[OVF_CAP];
__device__ int   g_ovf_dst[OVF_CAP];

// ---------------- ptx helpers ----------------
__device__ __forceinline__ u64 pack2(float lo, float hi) {
    u64 r; asm("mov.b64 %0, {%1, %2};" : "=l"(r) : "f"(lo), "f"(hi)); return r;
}
__device__ __forceinline__ float2 unpack2(u64 v) {
    float2 f; asm("mov.b64 {%0, %1}, %2;" : "=f"(f.x), "=f"(f.y) : "l"(v)); return f;
}
__device__ __forceinline__ void ffma2(u64& d, u64 a, u64 b) {
    asm("fma.rn.f32x2 %0, %1, %2, %0;" : "+l"(d) : "l"(a), "l"(b));
}
__device__ __forceinline__ void cp16s(uint32_t sa, const void* g) {
    asm volatile("cp.async.cg.shared.global [%0], [%1], 16;" :: "r"(sa), "l"(g));
}
#define CP_COMMIT() asm volatile("cp.async.commit_group;")
#define CP_WAIT(n)  asm volatile("cp.async.wait_group %0;" :: "n"(n))

__device__ __forceinline__ uint32_t smem_u32(const void* p) {
    uint32_t a;
    asm("{ .reg .u64 t; cvta.to.shared.u64 t, %1; cvt.u32.u64 %0, t; }" : "=r"(a) : "l"(p));
    return a;
}
__device__ __forceinline__ void ldsm4(uint32_t* r, uint32_t a) {
    asm volatile("ldmatrix.sync.aligned.m8n8.x4.shared.b16 {%0,%1,%2,%3}, [%4];"
                 : "=r"(r[0]), "=r"(r[1]), "=r"(r[2]), "=r"(r[3]) : "r"(a));
}
__device__ __forceinline__ void mma_f16(float* c, const uint32_t* a, const uint32_t* b) {
    asm volatile(
        "mma.sync.aligned.m16n8k16.row.col.f32.f16.f16.f32 "
        "{%0,%1,%2,%3}, {%4,%5,%6,%7}, {%8,%9}, {%0,%1,%2,%3};"
        : "+f"(c[0]), "+f"(c[1]), "+f"(c[2]), "+f"(c[3])
        : "r"(a[0]), "r"(a[1]), "r"(a[2]), "r"(a[3]), "r"(b[0]), "r"(b[1]));
}
__device__ __forceinline__ uint32_t h2pack(float a, float b) {
    __half2 h = __floats2half2_rn(a, b);
    return *(uint32_t*)&h;
}

// ---------------- kernels ----------------

// fc1_w transpose+fp16 convert (blocks 0..1567) + P/Q precompute (block 1568).
// Runs on a forked stream, overlapped with the edge pipeline.
__global__ void __launch_bounds__(256) k_cvtB(const float* __restrict__ B,
                                              const float* __restrict__ W1,
                                              const float* __restrict__ W2) {
    __shared__ float tile[32][129];
    int blk = blockIdx.x;
    int t = threadIdx.x;
    if (blk == 1568) {               // P/Q
        __shared__ float sp[4][64], sq[4][64];
        int j = t & 63, fg = t >> 6;
        float p = 0.f, q = 0.f;
#pragma unroll
        for (int ff = 0; ff < 8; ff++) {
            int f = fg * 8 + ff;
            float w = W1[f], v = W2[f * 64 + j];
            if (w > 0.f) p += v * w; else q += v * w;
        }
        sp[fg][j] = p; sq[fg][j] = q;
        __syncthreads();
        if (fg == 0) {
            g_P[j] = (sp[0][j] + sp[1][j]) + (sp[2][j] + sp[3][j]);
            g_Q[j] = (sq[0][j] + sq[1][j]) + (sq[2][j] + sq[3][j]);
        }
        return;
    }
    int k0 = blk * 32;
    for (int idx = t; idx < 4096; idx += 256) {
        int kr = idx >> 7, nn = idx & 127;
        tile[kr][nn] = B[(size_t)(k0 + kr) * 128 + nn];
    }
    __syncthreads();
    int n = t >> 1, ks = (t & 1) * 16;
    uint32_t ph[8];
#pragma unroll
    for (int q = 0; q < 8; q++)
        ph[q] = h2pack(tile[ks + 2 * q][n], tile[ks + 2 * q + 1][n]);
    size_t o = (size_t)n * KTOT + k0 + ks;
    *(uint4*)(g_fc1f + o)     = make_uint4(ph[0], ph[1], ph[2], ph[3]);
    *(uint4*)(g_fc1f + o + 8) = make_uint4(ph[4], ph[5], ph[6], ph[7]);
}

// Count in-degree and fill slot-major slot table. 4 edges per thread with
// vectorized int4 loads; batched independent atomics + scatter stores (MLP=4).
__global__ void k_count(const int* __restrict__ ei, int E) {
    __shared__ int s64;
    int t = threadIdx.x;
    if (t == 0) s64 = 1;
    __syncthreads();
    if (t < 64 && ei[2 * t + 1] != 0) s64 = 0;   // benign race (only writes 0)
    __syncthreads();
    int is64 = s64;
    int e0 = (blockIdx.x * blockDim.x + t) * 4;
    if (e0 >= E) return;
    int s[4], d[4];
    if (is64) {
        const int4* p = (const int4*)ei;           // int4 = 2 int64 elems
        int4 a = p[e0 >> 1];
        int4 b = p[(e0 >> 1) + 1];
        s[0] = a.x; s[1] = a.z; s[2] = b.x; s[3] = b.z;
        size_t db = ((size_t)E + e0) >> 1;
        int4 c = p[db];
        int4 f = p[db + 1];
        d[0] = c.x; d[1] = c.z; d[2] = f.x; d[3] = f.z;
    } else {
        int4 a = *(const int4*)(ei + e0);
        int4 b = *(const int4*)(ei + (size_t)E + e0);
        s[0] = a.x; s[1] = a.y; s[2] = a.z; s[3] = a.w;
        d[0] = b.x; d[1] = b.y; d[2] = b.z; d[3] = b.w;
    }
    int c4[4];
#pragma unroll
    for (int q = 0; q < 4; q++) {
        bool ok = (e0 + q < E) &&
                  (unsigned)s[q] < (unsigned)NN && (unsigned)d[q] < (unsigned)NN;
        c4[q] = ok ? atomicAdd(&g_cnt[d[q]], 1) : -1;
    }
#pragma unroll
    for (int q = 0; q < 4; q++) {
        if (c4[q] < 0) continue;
        if (c4[q] < CAP) {
            g_slots[(size_t)c4[q] * NN + d[q]] = s[q];
        } else {
            int o = atomicAdd(&g_ovf_n, 1);
            if (o < OVF_CAP) { g_ovf_src[o] = s[q]; g_ovf_dst[o] = d[q]; }
        }
    }
}

__global__ void k_dinv(const float* __restrict__ x, int n) {
    int i = blockIdx.x * blockDim.x + threadIdx.x;
    if (i < n) {
        float di = rsqrtf(1.0f + (float)g_cnt[i]);
        g_dinv[i] = di;
        g_xd[i] = x[i] * di;
    }
}

// Fused layer-1: 2 nodes per thread (i, i+n/2) -> interleaved gather chains.
// Fast path (b1==0, detected locally): store only (ap,an).
__global__ void k_l1(const float* __restrict__ W1,
                     const float* __restrict__ b1, int n) {
    __shared__ float w[32], b[32];
    __shared__ int nzf;
    int t = threadIdx.x;
    if (t == 0) nzf = 0;
    __syncthreads();
    if (t < 32) {
        w[t] = W1[t]; b[t] = b1[t];
        if (b[t] != 0.0f) nzf = 1;
    }
    __syncthreads();
    int b1nz = nzf;
    int h = n >> 1;
    int i0 = blockIdx.x * blockDim.x + t;
    if (i0 >= h) return;
    int i1 = i0 + h;
    int c0 = g_cnt[i0], c1 = g_cnt[i1];
    int m0 = c0 < CAP ? c0 : CAP;
    int m1 = c1 < CAP ? c1 : CAP;
    float s0 = 0.f, s1 = 0.f;
    int mm = m0 < m1 ? m0 : m1;
    int j = 0;
    for (; j + 8 <= mm; j += 8) {      // interleaved: 16 independent gathers
        int sa[8], sb[8];
#pragma unroll
        for (int q = 0; q < 8; q++) {
            sa[q] = g_slots[(size_t)(j + q) * NN + i0];
            sb[q] = g_slots[(size_t)(j + q) * NN + i1];
        }
        float va[8], vb[8];
#pragma unroll
        for (int q = 0; q < 8; q++) { va[q] = g_xd[sa[q]]; vb[q] = g_xd[sb[q]]; }
        s0 += ((va[0] + va[1]) + (va[2] + va[3])) + ((va[4] + va[5]) + (va[6] + va[7]));
        s1 += ((vb[0] + vb[1]) + (vb[2] + vb[3])) + ((vb[4] + vb[5]) + (vb[6] + vb[7]));
    }
    auto tail = [&](int i, int jj, int m, float sum) -> float {
        for (; jj + 4 <= m; jj += 4) {
            int t0 = g_slots[(size_t)(jj + 0) * NN + i];
            int t1 = g_slots[(size_t)(jj + 1) * NN + i];
            int t2 = g_slots[(size_t)(jj + 2) * NN + i];
            int t3 = g_slots[(size_t)(jj + 3) * NN + i];
            sum += (g_xd[t0] + g_xd[t1]) + (g_xd[t2] + g_xd[t3]);
        }
        for (; jj < m; jj++) sum += g_xd[g_slots[(size_t)jj * NN + i]];
        return sum;
    };
    s0 = tail(i0, j, m0, s0);
    s1 = tail(i1, j, m1, s1);
    if (c0 > CAP || c1 > CAP) {   // exactness path; essentially never taken
        int on = g_ovf_n; if (on > OVF_CAP) on = OVF_CAP;
        for (int e = 0; e < on; e++) {
            if (g_ovf_dst[e] == i0) s0 += g_xd[g_ovf_src[e]];
            if (g_ovf_dst[e] == i1) s1 += g_xd[g_ovf_src[e]];
        }
    }
    float d0 = g_dinv[i0], d1 = g_dinv[i1];
    float t0v = d0 * s0 + g_xd[i0] * d0;
    float t1v = d1 * s1 + g_xd[i1] * d1;
    if (!b1nz) {
        g_ac[i0] = make_float2(fmaxf(t0v, 0.f) * d0, fminf(t0v, 0.f) * d0);
        g_ac[i1] = make_float2(fmaxf(t1v, 0.f) * d1, fminf(t1v, 0.f) * d1);
        return;
    }
#pragma unroll
    for (int pass = 0; pass < 2; pass++) {
        int i = pass ? i1 : i0;
        float tt = pass ? t1v : t0v;
        float di = pass ? d1 : d0;
        float4* dst = (float4*)(g_h1 + (size_t)i * 32);
#pragma unroll
        for (int q = 0; q < 8; q++) {
            int f = q * 4;
            float4 r;
            r.x = fmaxf(tt * w[f + 0] + b[f + 0], 0.f) * di;
            r.y = fmaxf(tt * w[f + 1] + b[f + 1], 0.f) * di;
            r.z = fmaxf(tt * w[f + 2] + b[f + 2], 0.f) * di;
            r.w = fmaxf(tt * w[f + 3] + b[f + 3], 0.f) * di;
            dst[q] = r;
        }
    }
}

// FAST layer-2 (b1==0): 2 nodes per thread, interleaved float2 gather chains;
// writes ONLY the rank-2 state (s1,s2) per node. Re-zeroes g_cnt for next call.
__global__ void __launch_bounds__(256) k_l2f(const float* __restrict__ b1, int n) {
    __shared__ int nzf;
    int t = threadIdx.x;
    if (t == 0) nzf = 0;
    __syncthreads();
    if (t < 32 && b1[t] != 0.0f) nzf = 1;
    __syncthreads();
    if (nzf) return;
    int h = n >> 1;
    int i0 = blockIdx.x * blockDim.x + t;
    if (i0 >= h) return;
    int i1 = i0 + h;
    int c0 = g_cnt[i0], c1 = g_cnt[i1];
    int m0 = c0 < CAP ? c0 : CAP;
    int m1 = c1 < CAP ? c1 : CAP;
    float Ap0 = 0.f, An0 = 0.f, Ap1 = 0.f, An1 = 0.f;
    int mm = m0 < m1 ? m0 : m1;
    int j = 0;
    for (; j + 8 <= mm; j += 8) {      // interleaved: 16 independent gathers
        int sa[8], sb[8];
#pragma unroll
        for (int q = 0; q < 8; q++) {
            sa[q] = g_slots[(size_t)(j + q) * NN + i0];
            sb[q] = g_slots[(size_t)(j + q) * NN + i1];
        }
#pragma unroll
        for (int q = 0; q < 8; q++) {
            float2 va = g_ac[sa[q]], vb = g_ac[sb[q]];
            Ap0 += va.x; An0 += va.y;
            Ap1 += vb.x; An1 += vb.y;
        }
    }
    auto tail = [&](int i, int jj, int m, float& Ap, float& An) {
        for (; jj < m; jj++) {
            float2 v = g_ac[g_slots[(size_t)jj * NN + i]];
            Ap += v.x; An += v.y;
        }
    };
    tail(i0, j, m0, Ap0, An0);
    tail(i1, j, m1, Ap1, An1);
    if (c0 > CAP || c1 > CAP) {
        int on = g_ovf_n; if (on > OVF_CAP) on = OVF_CAP;
        for (int e = 0; e < on; e++) {
            if (g_ovf_dst[e] == i0) { float2 v = g_ac[g_ovf_src[e]]; Ap0 += v.x; An0 += v.y; }
            if (g_ovf_dst[e] == i1) { float2 v = g_ac[g_ovf_src[e]]; Ap1 += v.x; An1 += v.y; }
        }
    }
    g_cnt[i0] = 0;                 // re-zero for next call
    g_cnt[i1] = 0;
    float2 me0 = g_ac[i0], me1 = g_ac[i1];
    float d0 = g_dinv[i0], d1 = g_dinv[i1];
    g_s[i0] = make_float2(d0 * (Ap0 + me0.x), d0 * (An0 + me0.y));
    g_s[i1] = make_float2(d1 * (Ap1 + me1.x), d1 * (An1 + me1.y));
}

// FALLBACK layer-2 (b1!=0): generic warp-gather path, fp16 write-out to g_h2f.
__global__ void __launch_bounds__(256) k_l2(const float* __restrict__ W2,
                                            const float* __restrict__ b1,
                                            const float* __restrict__ b2) {
    __shared__ u64  w2p[32 * 32];
    __shared__ float h2t[32][65];
    __shared__ float b2s[64];
    __shared__ int nzf;
    int t = threadIdx.x;
    if (t == 0) nzf = 0;
    __syncthreads();
    if (t < 32 && b1[t] != 0.0f) nzf = 1;
    __syncthreads();
    if (!nzf) return;
    for (int idx = t; idx < 1024; idx += 256) {
        int f = idx >> 5, l = idx & 31;
        w2p[idx] = pack2(W2[f * 64 + l], W2[f * 64 + l + 32]);
    }
    if (t < 64) b2s[t] = b2[t];
    __syncthreads();

    int warp = t >> 5, lane = t & 31;
    int p = blockIdx.x;
    int gblk = blockIdx.y;

#pragma unroll 1
    for (int q = 0; q < 4; q++) {
        int gl = warp * 4 + q;
        int i = (gblk * 32 + gl) * 784 + p;
        float di = g_dinv[i];
        int c = g_cnt[i];
        int m = c < CAP ? c : CAP;
        float acc = 0.f;
        int j = 0;
        for (; j + 8 <= m; j += 8) {
            int ss[8];
#pragma unroll
            for (int qq = 0; qq < 8; qq++) ss[qq] = g_slots[(size_t)(j + qq) * NN + i];
            float v[8];
#pragma unroll
            for (int qq = 0; qq < 8; qq++) v[qq] = g_h1[(size_t)ss[qq] * 32 + lane];
            acc += ((v[0] + v[1]) + (v[2] + v[3])) + ((v[4] + v[5]) + (v[6] + v[7]));
        }
        for (; j < m; j++)
            acc += g_h1[(size_t)g_slots[(size_t)j * NN + i] * 32 + lane];
        if (c > CAP) {
            int on = g_ovf_n; if (on > OVF_CAP) on = OVF_CAP;
            for (int e = 0; e < on; e++)
                if (g_ovf_dst[e] == i)
                    acc += g_h1[(size_t)g_ovf_src[e] * 32 + lane];
        }
        if (lane == 0) g_cnt[i] = 0;   // re-zero for next call
        float u = di * (acc + g_h1[(size_t)i * 32 + lane]);

        u64 o0 = pack2(b2s[lane], b2s[lane + 32]);
        u64 o1 = 0ull;
#pragma unroll
        for (int f = 0; f < 32; f += 2) {
            float uf0 = __shfl_sync(0xffffffffu, u, f);
            float uf1 = __shfl_sync(0xffffffffu, u, f + 1);
            ffma2(o0, pack2(uf0, uf0), w2p[f * 32 + lane]);
            ffma2(o1, pack2(uf1, uf1), w2p[(f + 1) * 32 + lane]);
        }
        float2 a0 = unpack2(o0), a1 = unpack2(o1);
        h2t[gl][lane]      = fmaxf(a0.x + a1.x, 0.f);
        h2t[gl][lane + 32] = fmaxf(a0.y + a1.y, 0.f);
    }
    __syncthreads();
    for (int idx = t; idx < 512; idx += 256) {
        int gl = idx >> 4, f4 = (idx & 15) * 4;
        uint32_t p0 = h2pack(h2t[gl][f4],     h2t[gl][f4 + 1]);
        uint32_t p1 = h2pack(h2t[gl][f4 + 2], h2t[gl][f4 + 3]);
        size_t o = (size_t)(gblk * 32 + gl) * KTOT + p * 64 + f4;
        *(uint2*)(g_h2f + o) = make_uint2(p0, p1);
    }
}

// HMMA fp16 GEMM: C[512x128] = A[512xK] B[Kx128], fp32 accumulate.
// FAST path: A-tiles materialized on the fly from rank-2 state g_s + P/Q/b2
// (A never touches DRAM). FALLBACK: cp.async from g_h2f.
// Also resets g_ovf_n for the next call.
#define HG_BUF 20480     // per double-buffer half: A(10240) + B(10240), 80B rows
__global__ void __launch_bounds__(256) k_hgemm(const float* __restrict__ b1,
                                               const float* __restrict__ b2) {
    extern __shared__ __align__(16) char sm[];
    __shared__ float sP[64], sQ[64], sB[64];
    __shared__ int nzf;
    const int t = threadIdx.x;
    if (t == 0) {
        nzf = 0;
        if (blockIdx.x == 0 && blockIdx.y == 0) g_ovf_n = 0;
    }
    __syncthreads();
    if (t < 32 && b1[t] != 0.0f) nzf = 1;
    if (t >= 64 && t < 128) {
        int j = t - 64;
        sP[j] = g_P[j]; sQ[j] = g_Q[j]; sB[j] = b2[j];
    }
    __syncthreads();
    const int useS = !nzf;

    const int warp = t >> 5, lane = t & 31;
    const int warpM = warp & 3, warpN = warp >> 2;
    const int g0 = blockIdx.x * 128;
    const int sp = blockIdx.y;
    const int t0 = sp * 42 + (sp < 14 ? sp : 14);
    const int ntc = 42 + (sp < 14 ? 1 : 0);

    const uint32_t sb = smem_u32(sm);

    float C[2][8][4];
#pragma unroll
    for (int a = 0; a < 2; a++)
#pragma unroll
        for (int bq = 0; bq < 8; bq++)
#pragma unroll
            for (int cq = 0; cq < 4; cq++) C[a][bq][cq] = 0.f;

    // B loader (cp.async): 128 rows x 64B at buffer offset 10240
    auto load_B = [&](int ch, int buf) {
        const size_t kb = (size_t)(t0 + ch) * 32;
        const uint32_t base = sb + buf * HG_BUF + 10240;
#pragma unroll
        for (int i = 0; i < 2; i++) {
            int v = t + i * 256;
            int row = v >> 2, c16 = v & 3;
            cp16s(base + row * 80 + c16 * 16,
                  g_fc1f + (size_t)row * KTOT + kb + c16 * 8);
        }
    };
    // FAST A builder: h2[g, kb+ks] = relu(s1*P[j]+s2*Q[j]+b2[j]), j=j0+ks
    auto build_A = [&](int ch, int buf) {
        const int kb = (t0 + ch) * 32;
        const int p = kb >> 6, j0 = kb & 63;
        const int row = t >> 1, jh = (t & 1) * 16;
        float2 sv = g_s[(size_t)(g0 + row) * 784 + p];
        uint32_t pk[8];
#pragma unroll
        for (int q = 0; q < 8; q++) {
            int j = j0 + jh + 2 * q;
            float v0 = fmaxf(sv.x * sP[j]     + sv.y * sQ[j]     + sB[j],     0.f);
            float v1 = fmaxf(sv.x * sP[j + 1] + sv.y * sQ[j + 1] + sB[j + 1], 0.f);
            pk[q] = h2pack(v0, v1);
        }
        char* dst = sm + buf * HG_BUF + row * 80 + jh * 2;
        *(uint4*)dst        = make_uint4(pk[0], pk[1], pk[2], pk[3]);
        *(uint4*)(dst + 16) = make_uint4(pk[4], pk[5], pk[6], pk[7]);
    };
    // FALLBACK A loader (cp.async from g_h2f)
    auto load_A_fb = [&](int ch, int buf) {
        const size_t kb = (size_t)(t0 + ch) * 32;
        const uint32_t base = sb + buf * HG_BUF;
#pragma unroll
        for (int i = 0; i < 2; i++) {
            int v = t + i * 256;
            int row = v >> 2, c16 = v & 3;
            cp16s(base + row * 80 + c16 * 16,
                  g_h2f + (size_t)(g0 + row) * KTOT + kb + c16 * 8);
        }
    };

    // prologue: chunk 0
    load_B(0, 0);
    if (useS) { CP_COMMIT(); build_A(0, 0); }
    else      { load_A_fb(0, 0); CP_COMMIT(); }

#pragma unroll 1
    for (int ch = 0; ch < ntc; ch++) {
        if (ch + 1 < ntc) {
            const int nb = (ch + 1) & 1;
            load_B(ch + 1, nb);
            if (useS) { CP_COMMIT(); build_A(ch + 1, nb); }
            else      { load_A_fb(ch + 1, nb); CP_COMMIT(); }
            CP_WAIT(1);
        } else {
            CP_WAIT(0);
        }
        __syncthreads();

        const uint32_t bufB = sb + (ch & 1) * HG_BUF;
#pragma unroll
        for (int k16 = 0; k16 < 2; k16++) {
            const uint32_t kOff = (k16 * 16 + ((lane >> 4) << 3)) * 2;
            uint32_t ah[2][4];
#pragma unroll
            for (int mt = 0; mt < 2; mt++) {
                uint32_t rowo = (warpM * 32 + mt * 16 + (lane & 15)) * 80 + kOff;
                ldsm4(ah[mt], bufB + rowo);
            }
            uint32_t bh[8][2];
#pragma unroll
            for (int ntp = 0; ntp < 4; ntp++) {
                uint32_t rowo = (warpN * 64 + ntp * 16 + (lane & 15)) * 80 + kOff;
                uint32_t q[4];
                ldsm4(q, bufB + 10240 + rowo);
                bh[2 * ntp][0] = q[0]; bh[2 * ntp][1] = q[2];
                bh[2 * ntp + 1][0] = q[1]; bh[2 * ntp + 1][1] = q[3];
            }
#pragma unroll
            for (int mt = 0; mt < 2; mt++)
#pragma unroll
                for (int nt = 0; nt < 8; nt++)
                    mma_f16(C[mt][nt], ah[mt], bh[nt]);
        }
        __syncthreads();
    }

#pragma unroll
    for (int mt = 0; mt < 2; mt++) {
        int r0 = g0 + warpM * 32 + mt * 16 + (lane >> 2);
#pragma unroll
        for (int nt = 0; nt < 8; nt++) {
            int col = warpN * 64 + nt * 8 + (lane & 3) * 2;
            float* d = &g_part[((size_t)sp * NGRAPH + r0) * 128 + col];
            *(float2*)d             = make_float2(C[mt][nt][0], C[mt][nt][1]);
            *(float2*)(d + 8 * 128) = make_float2(C[mt][nt][2], C[mt][nt][3]);
        }
    }
}

// Reduce partials + fc1 bias + relu + fc2
__global__ void k_final(const float* __restrict__ fc1_b,
                        const float* __restrict__ fc2_w,
                        const float* __restrict__ fc2_b,
                        float* __restrict__ out) {
    int g = blockIdx.x;     // 512
    int j = threadIdx.x;    // 128
    float v = fc1_b[j];
#pragma unroll 2
    for (int s = 0; s < SPLITS; s++)
        v += g_part[((size_t)s * NGRAPH + g) * 128 + j];
    v = fmaxf(v, 0.f);
    __shared__ float f1[128];
    f1[j] = v;
    __syncthreads();
    if (j < 10) {
        float o = fc2_b[j];
#pragma unroll 16
        for (int tt = 0; tt < 128; tt++) o += f1[tt] * fc2_w[tt * 10 + j];
        out[g * 10 + j] = o;
    }
}

// ---------------- host launcher ----------------
extern "C" void kernel_launch(void* const* d_in, const int* in_sizes, int n_in,
                              void* d_out, int out_size) {
    const float* x     = (const float*)d_in[0];
    const int*   ei    = (const int*)d_in[1];     // int32 OR int64 (auto-detected)
    const float* W1    = (const float*)d_in[2];
    const float* b1    = (const float*)d_in[3];
    const float* W2    = (const float*)d_in[4];
    const float* b2    = (const float*)d_in[5];
    const float* fc1_w = (const float*)d_in[6];
    const float* fc1_b = (const float*)d_in[7];
    const float* fc2_w = (const float*)d_in[8];
    const float* fc2_b = (const float*)d_in[9];
    float* out = (float*)d_out;

    int n = in_sizes[0];          // 401408
    int E = in_sizes[1] / 2;      // 3211264

    static cudaStream_t s2 = nullptr;
    static cudaEvent_t ev0 = nullptr, ev1 = nullptr;
    if (!s2) {                    // created on first (non-captured) call
        cudaFuncSetAttribute(k_hgemm, cudaFuncAttributeMaxDynamicSharedMemorySize,
                             2 * HG_BUF);
        cudaStreamCreate(&s2);
        cudaEventCreateWithFlags(&ev0, cudaEventDisableTiming);
        cudaEventCreateWithFlags(&ev1, cudaEventDisableTiming);
    }

    // fork: fc1_w conversion + P/Q on s2, overlapped with the edge pipeline
    cudaEventRecord(ev0, 0);
    cudaStreamWaitEvent(s2, ev0, 0);
    k_cvtB<<<1569, 256, 0, s2>>>(fc1_w, W1, W2);
    cudaEventRecord(ev1, s2);

    k_count<<<(E / 4 + 255) / 256, 256>>>(ei, E);
    k_dinv<<<(n + 255) / 256, 256>>>(x, n);
    k_l1<<<(n / 2 + 255) / 256, 256>>>(W1, b1, n);
    k_l2f<<<(n / 2 + 255) / 256, 256>>>(b1, n);
    k_l2<<<dim3(784, 16), 256>>>(W2, b1, b2);

    cudaStreamWaitEvent(0, ev1, 0);   // join before g_P/g_fc1f consumers
    k_hgemm<<<dim3(4, SPLITS), 256, 2 * HG_BUF>>>(b1, b2);
    k_final<<<NGRAPH, 128>>>(fc1_b, fc2_w, fc2_b, out);
}

// round 15
// speedup vs baseline: 1.0543x; 1.0543x over previous
#include <cuda_runtime.h>
#include <cuda_bf16.h>
#include <cuda_fp16.h>
#include <cstdint>

// Problem constants (fixed by the dataset)
#define NN     401408          // nodes
#define EE     3211264         // edges
#define CAP    40              // slots per node (indegree ~ Poisson(8))
#define OVF_CAP 65536
#define KTOT   50176           // 784*64
#define NGRAPH 512
#define SPLITS 37              // split-K partitions over 1568 K-chunks of 32

typedef unsigned long long u64;

// ---------------- device scratch (static, no allocations) ----------------
// g_cnt / g_ovf_n rely on CUDA zero-init for call 1; later kernels of each
// call re-zero them for the next call (k_l2f/k_l2 -> g_cnt, k_hgemm -> g_ovf_n).
__device__ int   g_cnt[NN];
__device__ float g_dinv[NN];
__device__ float g_xd[NN];                                     // x*dinv
__device__ int   g_slots[(size_t)CAP * NN];                    // slot-major
__device__ __align__(16) float g_h1[(size_t)NN * 32];          // fallback path only
__device__ __align__(8)  float2 g_ac[NN];                      // (relu(tt)*di, min(tt,0)*di)
__device__ __align__(8)  float2 g_s[NN];                       // (s1, s2) post-aggregation
__device__ float g_P[64], g_Q[64];
__device__ __align__(16) __half g_h2f[(size_t)NGRAPH * KTOT];  // fallback path only
__device__ __align__(16) __half g_fc1f[(size_t)128 * KTOT];    // B^T fp16 [n][k]
__device__ __align__(16) float g_part[(size_t)SPLITS * NGRAPH * 128];
__device__ int   g_ovf_n;
__device__ int   g_ovf_src[OVF_CAP];
__device__ int   g_ovf_dst[OVF_CAP];

// ---------------- ptx helpers ----------------
__device__ __forceinline__ u64 pack2(float lo, float hi) {
    u64 r; asm("mov.b64 %0, {%1, %2};" : "=l"(r) : "f"(lo), "f"(hi)); return r;
}
__device__ __forceinline__ float2 unpack2(u64 v) {
    float2 f; asm("mov.b64 {%0, %1}, %2;" : "=f"(f.x), "=f"(f.y) : "l"(v)); return f;
}
__device__ __forceinline__ void ffma2(u64& d, u64 a, u64 b) {
    asm("fma.rn.f32x2 %0, %1, %2, %0;" : "+l"(d) : "l"(a), "l"(b));
}
__device__ __forceinline__ void cp16s(uint32_t sa, const void* g) {
    asm volatile("cp.async.cg.shared.global [%0], [%1], 16;" :: "r"(sa), "l"(g));
}
#define CP_COMMIT() asm volatile("cp.async.commit_group;")
#define CP_WAIT(n)  asm volatile("cp.async.wait_group %0;" :: "n"(n))

__device__ __forceinline__ uint32_t smem_u32(const void* p) {
    uint32_t a;
    asm("{ .reg .u64 t; cvta.to.shared.u64 t, %1; cvt.u32.u64 %0, t; }" : "=r"(a) : "l"(p));
    return a;
}
__device__ __forceinline__ void ldsm4(uint32_t* r, uint32_t a) {
    asm volatile("ldmatrix.sync.aligned.m8n8.x4.shared.b16 {%0,%1,%2,%3}, [%4];"
                 : "=r"(r[0]), "=r"(r[1]), "=r"(r[2]), "=r"(r[3]) : "r"(a));
}
__device__ __forceinline__ void mma_f16(float* c, const uint32_t* a, const uint32_t* b) {
    asm volatile(
        "mma.sync.aligned.m16n8k16.row.col.f32.f16.f16.f32 "
        "{%0,%1,%2,%3}, {%4,%5,%6,%7}, {%8,%9}, {%0,%1,%2,%3};"
        : "+f"(c[0]), "+f"(c[1]), "+f"(c[2]), "+f"(c[3])
        : "r"(a[0]), "r"(a[1]), "r"(a[2]), "r"(a[3]), "r"(b[0]), "r"(b[1]));
}
__device__ __forceinline__ uint32_t h2pack(float a, float b) {
    __half2 h = __floats2half2_rn(a, b);
    return *(uint32_t*)&h;
}

// ---------------- kernels ----------------

// fc1_w transpose+fp16 convert (blocks 0..1567) + P/Q precompute (block 1568).
// Runs on a forked stream, overlapped with the edge pipeline.
__global__ void __launch_bounds__(256) k_cvtB(const float* __restrict__ B,
                                              const float* __restrict__ W1,
                                              const float* __restrict__ W2) {
    __shared__ float tile[32][129];
    int blk = blockIdx.x;
    int t = threadIdx.x;
    if (blk == 1568) {               // P/Q
        __shared__ float sp[4][64], sq[4][64];
        int j = t & 63, fg = t >> 6;
        float p = 0.f, q = 0.f;
#pragma unroll
        for (int ff = 0; ff < 8; ff++) {
            int f = fg * 8 + ff;
            float w = W1[f], v = W2[f * 64 + j];
            if (w > 0.f) p += v * w; else q += v * w;
        }
        sp[fg][j] = p; sq[fg][j] = q;
        __syncthreads();
        if (fg == 0) {
            g_P[j] = (sp[0][j] + sp[1][j]) + (sp[2][j] + sp[3][j]);
            g_Q[j] = (sq[0][j] + sq[1][j]) + (sq[2][j] + sq[3][j]);
        }
        return;
    }
    int k0 = blk * 32;
    for (int idx = t; idx < 4096; idx += 256) {
        int kr = idx >> 7, nn = idx & 127;
        tile[kr][nn] = B[(size_t)(k0 + kr) * 128 + nn];
    }
    __syncthreads();
    int n = t >> 1, ks = (t & 1) * 16;
    uint32_t ph[8];
#pragma unroll
    for (int q = 0; q < 8; q++)
        ph[q] = h2pack(tile[ks + 2 * q][n], tile[ks + 2 * q + 1][n]);
    size_t o = (size_t)n * KTOT + k0 + ks;
    *(uint4*)(g_fc1f + o)     = make_uint4(ph[0], ph[1], ph[2], ph[3]);
    *(uint4*)(g_fc1f + o + 8) = make_uint4(ph[4], ph[5], ph[6], ph[7]);
}

// Count in-degree and fill slot-major slot table. 4 edges per thread with
// vectorized int4 loads; batched independent atomics + scatter stores (MLP=4).
__global__ void k_count(const int* __restrict__ ei, int E) {
    __shared__ int s64;
    int t = threadIdx.x;
    if (t == 0) s64 = 1;
    __syncthreads();
    if (t < 64 && ei[2 * t + 1] != 0) s64 = 0;   // benign race (only writes 0)
    __syncthreads();
    int is64 = s64;
    int e0 = (blockIdx.x * blockDim.x + t) * 4;
    if (e0 >= E) return;
    int s[4], d[4];
    if (is64) {
        const int4* p = (const int4*)ei;           // int4 = 2 int64 elems
        int4 a = p[e0 >> 1];
        int4 b = p[(e0 >> 1) + 1];
        s[0] = a.x; s[1] = a.z; s[2] = b.x; s[3] = b.z;
        size_t db = ((size_t)E + e0) >> 1;
        int4 c = p[db];
        int4 f = p[db + 1];
        d[0] = c.x; d[1] = c.z; d[2] = f.x; d[3] = f.z;
    } else {
        int4 a = *(const int4*)(ei + e0);
        int4 b = *(const int4*)(ei + (size_t)E + e0);
        s[0] = a.x; s[1] = a.y; s[2] = a.z; s[3] = a.w;
        d[0] = b.x; d[1] = b.y; d[2] = b.z; d[3] = b.w;
    }
    int c4[4];
#pragma unroll
    for (int q = 0; q < 4; q++) {
        bool ok = (e0 + q < E) &&
                  (unsigned)s[q] < (unsigned)NN && (unsigned)d[q] < (unsigned)NN;
        c4[q] = ok ? atomicAdd(&g_cnt[d[q]], 1) : -1;
    }
#pragma unroll
    for (int q = 0; q < 4; q++) {
        if (c4[q] < 0) continue;
        if (c4[q] < CAP) {
            g_slots[(size_t)c4[q] * NN + d[q]] = s[q];
        } else {
            int o = atomicAdd(&g_ovf_n, 1);
            if (o < OVF_CAP) { g_ovf_src[o] = s[q]; g_ovf_dst[o] = d[q]; }
        }
    }
}

// 4 nodes per thread, vectorized.
__global__ void k_dinv(const float* __restrict__ x, int n) {
    int i0 = (blockIdx.x * blockDim.x + threadIdx.x) * 4;
    if (i0 >= n) return;
    int4 c = *(const int4*)(g_cnt + i0);
    float4 xv = *(const float4*)(x + i0);
    float4 dv, xd;
    dv.x = rsqrtf(1.0f + (float)c.x);
    dv.y = rsqrtf(1.0f + (float)c.y);
    dv.z = rsqrtf(1.0f + (float)c.z);
    dv.w = rsqrtf(1.0f + (float)c.w);
    xd.x = xv.x * dv.x; xd.y = xv.y * dv.y;
    xd.z = xv.z * dv.z; xd.w = xv.w * dv.w;
    *(float4*)(g_dinv + i0) = dv;
    *(float4*)(g_xd + i0) = xd;
}

// Fused layer-1: 2 nodes per thread (i, i+n/2) -> interleaved gather chains.
// Fast path (b1==0, detected locally): store only (ap,an).
__global__ void k_l1(const float* __restrict__ W1,
                     const float* __restrict__ b1, int n) {
    __shared__ float w[32], b[32];
    __shared__ int nzf;
    int t = threadIdx.x;
    if (t == 0) nzf = 0;
    __syncthreads();
    if (t < 32) {
        w[t] = W1[t]; b[t] = b1[t];
        if (b[t] != 0.0f) nzf = 1;
    }
    __syncthreads();
    int b1nz = nzf;
    int h = n >> 1;
    int i0 = blockIdx.x * blockDim.x + t;
    if (i0 >= h) return;
    int i1 = i0 + h;
    int c0 = g_cnt[i0], c1 = g_cnt[i1];
    int m0 = c0 < CAP ? c0 : CAP;
    int m1 = c1 < CAP ? c1 : CAP;
    float s0 = 0.f, s1 = 0.f;
    int mm = m0 < m1 ? m0 : m1;
    int j = 0;
    for (; j + 8 <= mm; j += 8) {      // interleaved: 16 independent gathers
        int sa[8], sb[8];
#pragma unroll
        for (int q = 0; q < 8; q++) {
            sa[q] = g_slots[(size_t)(j + q) * NN + i0];
            sb[q] = g_slots[(size_t)(j + q) * NN + i1];
        }
        float va[8], vb[8];
#pragma unroll
        for (int q = 0; q < 8; q++) { va[q] = g_xd[sa[q]]; vb[q] = g_xd[sb[q]]; }
        s0 += ((va[0] + va[1]) + (va[2] + va[3])) + ((va[4] + va[5]) + (va[6] + va[7]));
        s1 += ((vb[0] + vb[1]) + (vb[2] + vb[3])) + ((vb[4] + vb[5]) + (vb[6] + vb[7]));
    }
    auto tail = [&](int i, int jj, int m, float sum) -> float {
        for (; jj + 4 <= m; jj += 4) {
            int t0 = g_slots[(size_t)(jj + 0) * NN + i];
            int t1 = g_slots[(size_t)(jj + 1) * NN + i];
            int t2 = g_slots[(size_t)(jj + 2) * NN + i];
            int t3 = g_slots[(size_t)(jj + 3) * NN + i];
            sum += (g_xd[t0] + g_xd[t1]) + (g_xd[t2] + g_xd[t3]);
        }
        for (; jj < m; jj++) sum += g_xd[g_slots[(size_t)jj * NN + i]];
        return sum;
    };
    s0 = tail(i0, j, m0, s0);
    s1 = tail(i1, j, m1, s1);
    if (c0 > CAP || c1 > CAP) {   // exactness path; essentially never taken
        int on = g_ovf_n; if (on > OVF_CAP) on = OVF_CAP;
        for (int e = 0; e < on; e++) {
            if (g_ovf_dst[e] == i0) s0 += g_xd[g_ovf_src[e]];
            if (g_ovf_dst[e] == i1) s1 += g_xd[g_ovf_src[e]];
        }
    }
    float d0 = g_dinv[i0], d1 = g_dinv[i1];
    float t0v = d0 * s0 + g_xd[i0] * d0;
    float t1v = d1 * s1 + g_xd[i1] * d1;
    if (!b1nz) {
        g_ac[i0] = make_float2(fmaxf(t0v, 0.f) * d0, fminf(t0v, 0.f) * d0);
        g_ac[i1] = make_float2(fmaxf(t1v, 0.f) * d1, fminf(t1v, 0.f) * d1);
        return;
    }
#pragma unroll
    for (int pass = 0; pass < 2; pass++) {
        int i = pass ? i1 : i0;
        float tt = pass ? t1v : t0v;
        float di = pass ? d1 : d0;
        float4* dst = (float4*)(g_h1 + (size_t)i * 32);
#pragma unroll
        for (int q = 0; q < 8; q++) {
            int f = q * 4;
            float4 r;
            r.x = fmaxf(tt * w[f + 0] + b[f + 0], 0.f) * di;
            r.y = fmaxf(tt * w[f + 1] + b[f + 1], 0.f) * di;
            r.z = fmaxf(tt * w[f + 2] + b[f + 2], 0.f) * di;
            r.w = fmaxf(tt * w[f + 3] + b[f + 3], 0.f) * di;
            dst[q] = r;
        }
    }
}

// FAST layer-2 (b1==0): 1 node per thread (proven round-13 form), float2
// gathers, writes ONLY rank-2 state (s1,s2). Re-zeroes g_cnt for next call.
__global__ void __launch_bounds__(256) k_l2f(const float* __restrict__ b1, int n) {
    __shared__ int nzf;
    int t = threadIdx.x;
    if (t == 0) nzf = 0;
    __syncthreads();
    if (t < 32 && b1[t] != 0.0f) nzf = 1;
    __syncthreads();
    if (nzf) return;
    int i = blockIdx.x * blockDim.x + t;
    if (i >= n) return;
    int c = g_cnt[i];
    int m = c < CAP ? c : CAP;
    float Ap = 0.f, An = 0.f;
    int j = 0;
    for (; j + 8 <= m; j += 8) {
        int ss[8];
#pragma unroll
        for (int q = 0; q < 8; q++) ss[q] = g_slots[(size_t)(j + q) * NN + i];
#pragma unroll
        for (int q = 0; q < 8; q++) {
            float2 v = g_ac[ss[q]];
            Ap += v.x; An += v.y;
        }
    }
    for (; j < m; j++) {
        float2 v = g_ac[g_slots[(size_t)j * NN + i]];
        Ap += v.x; An += v.y;
    }
    if (c > CAP) {
        int on = g_ovf_n; if (on > OVF_CAP) on = OVF_CAP;
        for (int e = 0; e < on; e++)
            if (g_ovf_dst[e] == i) {
                float2 v = g_ac[g_ovf_src[e]];
                Ap += v.x; An += v.y;
            }
    }
    g_cnt[i] = 0;                 // re-zero for next call
    float2 me = g_ac[i];
    float di = g_dinv[i];
    g_s[i] = make_float2(di * (Ap + me.x), di * (An + me.y));
}

// FALLBACK layer-2 (b1!=0): generic warp-gather path, fp16 write-out to g_h2f.
// Grid reduced 16x: each block loops over 16 p-values (cheap fast-path exit).
__global__ void __launch_bounds__(256) k_l2(const float* __restrict__ W2,
                                            const float* __restrict__ b1,
                                            const float* __restrict__ b2) {
    __shared__ u64  w2p[32 * 32];
    __shared__ float h2t[32][65];
    __shared__ float b2s[64];
    __shared__ int nzf;
    int t = threadIdx.x;
    if (t == 0) nzf = 0;
    __syncthreads();
    if (t < 32 && b1[t] != 0.0f) nzf = 1;
    __syncthreads();
    if (!nzf) return;
    for (int idx = t; idx < 1024; idx += 256) {
        int f = idx >> 5, l = idx & 31;
        w2p[idx] = pack2(W2[f * 64 + l], W2[f * 64 + l + 32]);
    }
    if (t < 64) b2s[t] = b2[t];
    __syncthreads();

    int warp = t >> 5, lane = t & 31;
    int gblk = blockIdx.y;

#pragma unroll 1
    for (int pp = 0; pp < 16; pp++) {
        int p = blockIdx.x * 16 + pp;
#pragma unroll 1
        for (int q = 0; q < 4; q++) {
            int gl = warp * 4 + q;
            int i = (gblk * 32 + gl) * 784 + p;
            float di = g_dinv[i];
            int c = g_cnt[i];
            int m = c < CAP ? c : CAP;
            float acc = 0.f;
            int j = 0;
            for (; j + 8 <= m; j += 8) {
                int ss[8];
#pragma unroll
                for (int qq = 0; qq < 8; qq++) ss[qq] = g_slots[(size_t)(j + qq) * NN + i];
                float v[8];
#pragma unroll
                for (int qq = 0; qq < 8; qq++) v[qq] = g_h1[(size_t)ss[qq] * 32 + lane];
                acc += ((v[0] + v[1]) + (v[2] + v[3])) + ((v[4] + v[5]) + (v[6] + v[7]));
            }
            for (; j < m; j++)
                acc += g_h1[(size_t)g_slots[(size_t)j * NN + i] * 32 + lane];
            if (c > CAP) {
                int on = g_ovf_n; if (on > OVF_CAP) on = OVF_CAP;
                for (int e = 0; e < on; e++)
                    if (g_ovf_dst[e] == i)
                        acc += g_h1[(size_t)g_ovf_src[e] * 32 + lane];
            }
            if (lane == 0) g_cnt[i] = 0;   // re-zero for next call
            float u = di * (acc + g_h1[(size_t)i * 32 + lane]);

            u64 o0 = pack2(b2s[lane], b2s[lane + 32]);
            u64 o1 = 0ull;
#pragma unroll
            for (int f = 0; f < 32; f += 2) {
                float uf0 = __shfl_sync(0xffffffffu, u, f);
                float uf1 = __shfl_sync(0xffffffffu, u, f + 1);
                ffma2(o0, pack2(uf0, uf0), w2p[f * 32 + lane]);
                ffma2(o1, pack2(uf1, uf1), w2p[(f + 1) * 32 + lane]);
            }
            float2 a0 = unpack2(o0), a1 = unpack2(o1);
            h2t[gl][lane]      = fmaxf(a0.x + a1.x, 0.f);
            h2t[gl][lane + 32] = fmaxf(a0.y + a1.y, 0.f);
        }
        __syncthreads();
        for (int idx = t; idx < 512; idx += 256) {
            int gl = idx >> 4, f4 = (idx & 15) * 4;
            uint32_t p0 = h2pack(h2t[gl][f4],     h2t[gl][f4 + 1]);
            uint32_t p1 = h2pack(h2t[gl][f4 + 2], h2t[gl][f4 + 3]);
            size_t o = (size_t)(gblk * 32 + gl) * KTOT + p * 64 + f4;
            *(uint2*)(g_h2f + o) = make_uint2(p0, p1);
        }
        __syncthreads();
    }
}

// HMMA fp16 GEMM: C[512x128] = A[512xK] B[Kx128], fp32 accumulate.
// FAST path: A-tiles materialized on the fly from rank-2 state g_s + P/Q/b2
// (A never touches DRAM). FALLBACK: cp.async from g_h2f.
// Also resets g_ovf_n for the next call.
#define HG_BUF 20480     // per double-buffer half: A(10240) + B(10240), 80B rows
__global__ void __launch_bounds__(256) k_hgemm(const float* __restrict__ b1,
                                               const float* __restrict__ b2) {
    extern __shared__ __align__(16) char sm[];
    __shared__ float sP[64], sQ[64], sB[64];
    __shared__ int nzf;
    const int t = threadIdx.x;
    if (t == 0) {
        nzf = 0;
        if (blockIdx.x == 0 && blockIdx.y == 0) g_ovf_n = 0;
    }
    __syncthreads();
    if (t < 32 && b1[t] != 0.0f) nzf = 1;
    if (t >= 64 && t < 128) {
        int j = t - 64;
        sP[j] = g_P[j]; sQ[j] = g_Q[j]; sB[j] = b2[j];
    }
    __syncthreads();
    const int useS = !nzf;

    const int warp = t >> 5, lane = t & 31;
    const int warpM = warp & 3, warpN = warp >> 2;
    const int g0 = blockIdx.x * 128;
    const int sp = blockIdx.y;
    const int t0 = sp * 42 + (sp < 14 ? sp : 14);
    const int ntc = 42 + (sp < 14 ? 1 : 0);

    const uint32_t sb = smem_u32(sm);

    float C[2][8][4];
#pragma unroll
    for (int a = 0; a < 2; a++)
#pragma unroll
        for (int bq = 0; bq < 8; bq++)
#pragma unroll
            for (int cq = 0; cq < 4; cq++) C[a][bq][cq] = 0.f;

    // B loader (cp.async): 128 rows x 64B at buffer offset 10240
    auto load_B = [&](int ch, int buf) {
        const size_t kb = (size_t)(t0 + ch) * 32;
        const uint32_t base = sb + buf * HG_BUF + 10240;
#pragma unroll
        for (int i = 0; i < 2; i++) {
            int v = t + i * 256;
            int row = v >> 2, c16 = v & 3;
            cp16s(base + row * 80 + c16 * 16,
                  g_fc1f + (size_t)row * KTOT + kb + c16 * 8);
        }
    };
    // FAST A builder: h2[g, kb+ks] = relu(s1*P[j]+s2*Q[j]+b2[j]), j=j0+ks
    auto build_A = [&](int ch, int buf) {
        const int kb = (t0 + ch) * 32;
        const int p = kb >> 6, j0 = kb & 63;
        const int row = t >> 1, jh = (t & 1) * 16;
        float2 sv = g_s[(size_t)(g0 + row) * 784 + p];
        uint32_t pk[8];
#pragma unroll
        for (int q = 0; q < 8; q++) {
            int j = j0 + jh + 2 * q;
            float v0 = fmaxf(sv.x * sP[j]     + sv.y * sQ[j]     + sB[j],     0.f);
            float v1 = fmaxf(sv.x * sP[j + 1] + sv.y * sQ[j + 1] + sB[j + 1], 0.f);
            pk[q] = h2pack(v0, v1);
        }
        char* dst = sm + buf * HG_BUF + row * 80 + jh * 2;
        *(uint4*)dst        = make_uint4(pk[0], pk[1], pk[2], pk[3]);
        *(uint4*)(dst + 16) = make_uint4(pk[4], pk[5], pk[6], pk[7]);
    };
    // FALLBACK A loader (cp.async from g_h2f)
    auto load_A_fb = [&](int ch, int buf) {
        const size_t kb = (size_t)(t0 + ch) * 32;
        const uint32_t base = sb + buf * HG_BUF;
#pragma unroll
        for (int i = 0; i < 2; i++) {
            int v = t + i * 256;
            int row = v >> 2, c16 = v & 3;
            cp16s(base + row * 80 + c16 * 16,
                  g_h2f + (size_t)(g0 + row) * KTOT + kb + c16 * 8);
        }
    };

    // prologue: chunk 0
    load_B(0, 0);
    if (useS) { CP_COMMIT(); build_A(0, 0); }
    else      { load_A_fb(0, 0); CP_COMMIT(); }

#pragma unroll 1
    for (int ch = 0; ch < ntc; ch++) {
        if (ch + 1 < ntc) {
            const int nb = (ch + 1) & 1;
            load_B(ch + 1, nb);
            if (useS) { CP_COMMIT(); build_A(ch + 1, nb); }
            else      { load_A_fb(ch + 1, nb); CP_COMMIT(); }
            CP_WAIT(1);
        } else {
            CP_WAIT(0);
        }
        __syncthreads();

        const uint32_t bufB = sb + (ch & 1) * HG_BUF;
#pragma unroll
        for (int k16 = 0; k16 < 2; k16++) {
            const uint32_t kOff = (k16 * 16 + ((lane >> 4) << 3)) * 2;
            uint32_t ah[2][4];
#pragma unroll
            for (int mt = 0; mt < 2; mt++) {
                uint32_t rowo = (warpM * 32 + mt * 16 + (lane & 15)) * 80 + kOff;
                ldsm4(ah[mt], bufB + rowo);
            }
            uint32_t bh[8][2];
#pragma unroll
            for (int ntp = 0; ntp < 4; ntp++) {
                uint32_t rowo = (warpN * 64 + ntp * 16 + (lane & 15)) * 80 + kOff;
                uint32_t q[4];
                ldsm4(q, bufB + 10240 + rowo);
                bh[2 * ntp][0] = q[0]; bh[2 * ntp][1] = q[2];
                bh[2 * ntp + 1][0] = q[1]; bh[2 * ntp + 1][1] = q[3];
            }
#pragma unroll
            for (int mt = 0; mt < 2; mt++)
#pragma unroll
                for (int nt = 0; nt < 8; nt++)
                    mma_f16(C[mt][nt], ah[mt], bh[nt]);
        }
        __syncthreads();
    }

#pragma unroll
    for (int mt = 0; mt < 2; mt++) {
        int r0 = g0 + warpM * 32 + mt * 16 + (lane >> 2);
#pragma unroll
        for (int nt = 0; nt < 8; nt++) {
            int col = warpN * 64 + nt * 8 + (lane & 3) * 2;
            float* d = &g_part[((size_t)sp * NGRAPH + r0) * 128 + col];
            *(float2*)d             = make_float2(C[mt][nt][0], C[mt][nt][1]);
            *(float2*)(d + 8 * 128) = make_float2(C[mt][nt][2], C[mt][nt][3]);
        }
    }
}

// Reduce partials + fc1 bias + relu + fc2
__global__ void k_final(const float* __restrict__ fc1_b,
                        const float* __restrict__ fc2_w,
                        const float* __restrict__ fc2_b,
                        float* __restrict__ out) {
    int g = blockIdx.x;     // 512
    int j = threadIdx.x;    // 128
    float v = fc1_b[j];
#pragma unroll 2
    for (int s = 0; s < SPLITS; s++)
        v += g_part[((size_t)s * NGRAPH + g) * 128 + j];
    v = fmaxf(v, 0.f);
    __shared__ float f1[128];
    f1[j] = v;
    __syncthreads();
    if (j < 10) {
        float o = fc2_b[j];
#pragma unroll 16
        for (int tt = 0; tt < 128; tt++) o += f1[tt] * fc2_w[tt * 10 + j];
        out[g * 10 + j] = o;
    }
}

// ---------------- host launcher ----------------
extern "C" void kernel_launch(void* const* d_in, const int* in_sizes, int n_in,
                              void* d_out, int out_size) {
    const float* x     = (const float*)d_in[0];
    const int*   ei    = (const int*)d_in[1];     // int32 OR int64 (auto-detected)
    const float* W1    = (const float*)d_in[2];
    const float* b1    = (const float*)d_in[3];
    const float* W2    = (const float*)d_in[4];
    const float* b2    = (const float*)d_in[5];
    const float* fc1_w = (const float*)d_in[6];
    const float* fc1_b = (const float*)d_in[7];
    const float* fc2_w = (const float*)d_in[8];
    const float* fc2_b = (const float*)d_in[9];
    float* out = (float*)d_out;

    int n = in_sizes[0];          // 401408
    int E = in_sizes[1] / 2;      // 3211264

    static cudaStream_t s2 = nullptr;
    static cudaEvent_t ev0 = nullptr, ev1 = nullptr;
    if (!s2) {                    // created on first (non-captured) call
        cudaFuncSetAttribute(k_hgemm, cudaFuncAttributeMaxDynamicSharedMemorySize,
                             2 * HG_BUF);
        cudaStreamCreate(&s2);
        cudaEventCreateWithFlags(&ev0, cudaEventDisableTiming);
        cudaEventCreateWithFlags(&ev1, cudaEventDisableTiming);
    }

    // fork: fc1_w conversion + P/Q on s2, overlapped with the edge pipeline
    cudaEventRecord(ev0, 0);
    cudaStreamWaitEvent(s2, ev0, 0);
    k_cvtB<<<1569, 256, 0, s2>>>(fc1_w, W1, W2);
    cudaEventRecord(ev1, s2);

    k_count<<<(E / 4 + 255) / 256, 256>>>(ei, E);
    k_dinv<<<(n / 4 + 255) / 256, 256>>>(x, n);
    k_l1<<<(n / 2 + 255) / 256, 256>>>(W1, b1, n);
    k_l2f<<<(n + 255) / 256, 256>>>(b1, n);
    k_l2<<<dim3(49, 16), 256>>>(W2, b1, b2);

    cudaStreamWaitEvent(0, ev1, 0);   // join before g_P/g_fc1f consumers
    k_hgemm<<<dim3(4, SPLITS), 256, 2 * HG_BUF>>>(b1, b2);
    k_final<<<NGRAPH, 128>>>(fc1_b, fc2_w, fc2_b, out);
}